// round 6
// baseline (speedup 1.0000x reference)
#include <cuda_runtime.h>
#include <math.h>

// Problem constants
#define Bz 2
#define Tz 2048
#define Cz 768
#define Hz 12
#define Dz 64
#define BT (Bz * Tz)     // 4096
#define N3 (3 * Cz)      // 2304

#define F32_NEG_INF (__int_as_float(0xff800000))

// Scratch (allocation-free rule: device globals)
__device__ float g_q[Bz * Hz * Tz * Dz];
__device__ float g_k[Bz * Hz * Tz * Dz];
__device__ float g_v[Bz * Hz * Tz * Dz];
__device__ float g_y[BT * Cz];

// ---------------------------------------------------------------------------
// Kernel 1: QKV GEMM.  qkv = x @ c_attn_w + b, scattered into g_q/g_k/g_v
// laid out [B, H, T, D].  M=4096, N=2304, K=768. 128x128 tile, 8x8 micro.
// ---------------------------------------------------------------------------
__global__ __launch_bounds__(256, 2)
void qkv_kernel(const float* __restrict__ X,
                const float* __restrict__ W,
                const float* __restrict__ bias)
{
    __shared__ float As[8][128];
    __shared__ float Bs[8][128];

    const int tid = threadIdx.x;
    const int tx = tid & 15;
    const int ty = tid >> 4;
    const int m0 = blockIdx.y * 128;
    const int n0 = blockIdx.x * 128;

    float acc[8][8] = {};

    const int a_row = tid >> 1;          // 0..127
    const int a_k4  = (tid & 1) * 4;     // 0 or 4
    const int b_k   = tid >> 5;          // 0..7
    const int b_col = (tid & 31) * 4;    // 0..124

    for (int k0 = 0; k0 < Cz; k0 += 8) {
        float4 av = *(const float4*)&X[(size_t)(m0 + a_row) * Cz + k0 + a_k4];
        As[a_k4 + 0][a_row] = av.x;
        As[a_k4 + 1][a_row] = av.y;
        As[a_k4 + 2][a_row] = av.z;
        As[a_k4 + 3][a_row] = av.w;
        *(float4*)&Bs[b_k][b_col] =
            *(const float4*)&W[(size_t)(k0 + b_k) * N3 + n0 + b_col];
        __syncthreads();

        #pragma unroll
        for (int kk = 0; kk < 8; kk++) {
            float a[8], b[8];
            *(float4*)&a[0] = *(float4*)&As[kk][ty * 8];
            *(float4*)&a[4] = *(float4*)&As[kk][ty * 8 + 4];
            *(float4*)&b[0] = *(float4*)&Bs[kk][tx * 8];
            *(float4*)&b[4] = *(float4*)&Bs[kk][tx * 8 + 4];
            #pragma unroll
            for (int r = 0; r < 8; r++)
                #pragma unroll
                for (int c = 0; c < 8; c++)
                    acc[r][c] += a[r] * b[c];
        }
        __syncthreads();
    }

    // Epilogue: bias + scatter into q/k/v [B,H,T,D].
    // This thread's 8 columns stay within one 64-wide head chunk.
    const int cb   = n0 + tx * 8;        // column in [0, 2304)
    const int part = cb / Cz;            // 0=q,1=k,2=v
    const int cc   = cb % Cz;
    const int h    = cc / Dz;
    const int d0   = cc % Dz;
    float* dst = (part == 0) ? g_q : ((part == 1) ? g_k : g_v);

    float bb[8];
    #pragma unroll
    for (int c = 0; c < 8; c++) bb[c] = bias[cb + c];

    #pragma unroll
    for (int r = 0; r < 8; r++) {
        const int m  = m0 + ty * 8 + r;
        const int bi = m >> 11;          // / 2048
        const int t  = m & 2047;
        float* p = dst + ((size_t)(bi * Hz + h) * Tz + t) * Dz + d0;
        float4 o0 = make_float4(acc[r][0] + bb[0], acc[r][1] + bb[1],
                                acc[r][2] + bb[2], acc[r][3] + bb[3]);
        float4 o1 = make_float4(acc[r][4] + bb[4], acc[r][5] + bb[5],
                                acc[r][6] + bb[6], acc[r][7] + bb[7]);
        *(float4*)p       = o0;
        *(float4*)(p + 4) = o1;
    }
}

// ---------------------------------------------------------------------------
// Kernel 2: Flash attention, fp32. One block = 64 q rows of one (b,h).
// Online softmax. Writes y pre-proj into g_y [B, T, C].
// ---------------------------------------------------------------------------
#define APAD 68
struct AttnSmem {
    float Qt[64][APAD];   // [d][i], pre-scaled by 1/sqrt(D)
    float Kt[64][APAD];   // [d][j]
    float Vs[64][APAD];   // [j][d]
    float Ss[64][APAD];   // scores -> probs
    float m_s[64];
    float l_s[64];
    float alpha_s[64];
};

__global__ __launch_bounds__(256, 2)
void attn_kernel()
{
    extern __shared__ char smbuf[];
    AttnSmem& s = *reinterpret_cast<AttnSmem*>(smbuf);

    const int tid = threadIdx.x;
    const int tx = tid & 15;
    const int ty = tid >> 4;
    const int qt = blockIdx.x;           // q tile (64 rows)
    const int bh = blockIdx.y;           // 0..23
    const int b  = bh / Hz;
    const int h  = bh % Hz;

    const float* Q = g_q + (size_t)bh * Tz * Dz;
    const float* K = g_k + (size_t)bh * Tz * Dz;
    const float* V = g_v + (size_t)bh * Tz * Dz;

    // Load Q tile transposed, pre-scaled by 1/sqrt(64)
    for (int idx = tid; idx < 64 * 16; idx += 256) {
        const int i  = idx >> 4;
        const int d4 = (idx & 15) * 4;
        float4 val = *(const float4*)&Q[(size_t)(qt * 64 + i) * Dz + d4];
        s.Qt[d4 + 0][i] = val.x * 0.125f;
        s.Qt[d4 + 1][i] = val.y * 0.125f;
        s.Qt[d4 + 2][i] = val.z * 0.125f;
        s.Qt[d4 + 3][i] = val.w * 0.125f;
    }
    if (tid < 64) { s.m_s[tid] = F32_NEG_INF; s.l_s[tid] = 0.0f; }

    float acc[4][4] = {};
    const int row = tid >> 2;            // 0..63
    const int seg = tid & 3;             // quarter of the row
    const float L2E = 1.4426950408889634f;
    __syncthreads();

    for (int kt = 0; kt <= qt; kt++) {
        // Load K transposed and V natural
        for (int idx = tid; idx < 1024; idx += 256) {
            const int j  = idx >> 4;
            const int d4 = (idx & 15) * 4;
            float4 val = *(const float4*)&K[(size_t)(kt * 64 + j) * Dz + d4];
            s.Kt[d4 + 0][j] = val.x;
            s.Kt[d4 + 1][j] = val.y;
            s.Kt[d4 + 2][j] = val.z;
            s.Kt[d4 + 3][j] = val.w;
        }
        for (int idx = tid; idx < 1024; idx += 256) {
            const int j  = idx >> 4;
            const int d4 = (idx & 15) * 4;
            *(float4*)&s.Vs[j][d4] =
                *(const float4*)&V[(size_t)(kt * 64 + j) * Dz + d4];
        }
        __syncthreads();

        // S = (Q*scale) @ K^T   (4x4 microtile per thread)
        float sv[4][4] = {};
        #pragma unroll 8
        for (int d = 0; d < 64; d++) {
            float4 af = *(float4*)&s.Qt[d][ty * 4];
            float4 bf = *(float4*)&s.Kt[d][tx * 4];
            float aa[4] = {af.x, af.y, af.z, af.w};
            float bb[4] = {bf.x, bf.y, bf.z, bf.w};
            #pragma unroll
            for (int r = 0; r < 4; r++)
                #pragma unroll
                for (int c = 0; c < 4; c++)
                    sv[r][c] += aa[r] * bb[c];
        }
        if (kt == qt) {
            #pragma unroll
            for (int r = 0; r < 4; r++)
                #pragma unroll
                for (int c = 0; c < 4; c++)
                    if (tx * 4 + c > ty * 4 + r) sv[r][c] = F32_NEG_INF;
        }
        #pragma unroll
        for (int r = 0; r < 4; r++)
            *(float4*)&s.Ss[ty * 4 + r][tx * 4] =
                make_float4(sv[r][0], sv[r][1], sv[r][2], sv[r][3]);
        __syncthreads();

        // Online softmax: 4 threads per row (quad reduce via shfl)
        float mx = F32_NEG_INF;
        #pragma unroll
        for (int e = 0; e < 16; e++)
            mx = fmaxf(mx, s.Ss[row][seg * 16 + e]);
        mx = fmaxf(mx, __shfl_xor_sync(0xffffffffu, mx, 1));
        mx = fmaxf(mx, __shfl_xor_sync(0xffffffffu, mx, 2));
        const float mold = s.m_s[row];
        const float mnew = fmaxf(mold, mx);
        float sum = 0.0f;
        #pragma unroll
        for (int e = 0; e < 16; e++) {
            float p = exp2f((s.Ss[row][seg * 16 + e] - mnew) * L2E);
            s.Ss[row][seg * 16 + e] = p;
            sum += p;
        }
        sum += __shfl_xor_sync(0xffffffffu, sum, 1);
        sum += __shfl_xor_sync(0xffffffffu, sum, 2);
        if (seg == 0) {
            const float alpha = exp2f((mold - mnew) * L2E);
            s.alpha_s[row] = alpha;
            s.l_s[row] = s.l_s[row] * alpha + sum;
            s.m_s[row] = mnew;
        }
        __syncthreads();

        // Rescale O and accumulate P @ V
        float ar[4];
        #pragma unroll
        for (int r = 0; r < 4; r++) ar[r] = s.alpha_s[ty * 4 + r];
        #pragma unroll
        for (int r = 0; r < 4; r++)
            #pragma unroll
            for (int c = 0; c < 4; c++)
                acc[r][c] *= ar[r];

        #pragma unroll 8
        for (int kk = 0; kk < 64; kk++) {
            float4 vf = *(float4*)&s.Vs[kk][tx * 4];
            float vb[4] = {vf.x, vf.y, vf.z, vf.w};
            float p[4];
            #pragma unroll
            for (int r = 0; r < 4; r++) p[r] = s.Ss[ty * 4 + r][kk];
            #pragma unroll
            for (int r = 0; r < 4; r++)
                #pragma unroll
                for (int c = 0; c < 4; c++)
                    acc[r][c] += p[r] * vb[c];
        }
        __syncthreads();
    }

    // Normalize and write y[b, t, h*D + d]
    float inv[4];
    #pragma unroll
    for (int r = 0; r < 4; r++) inv[r] = 1.0f / s.l_s[ty * 4 + r];
    #pragma unroll
    for (int r = 0; r < 4; r++) {
        const int tglob = qt * 64 + ty * 4 + r;
        float4 o = make_float4(acc[r][0] * inv[r], acc[r][1] * inv[r],
                               acc[r][2] * inv[r], acc[r][3] * inv[r]);
        *(float4*)&g_y[((size_t)b * Tz + tglob) * Cz + h * Dz + tx * 4] = o;
    }
}

// ---------------------------------------------------------------------------
// Kernel 3: output projection. out = g_y @ c_proj_w + b.
// M=4096, N=768, K=768. 64x128 tile, 4x8 micro. grid (6, 64).
// ---------------------------------------------------------------------------
__global__ __launch_bounds__(256, 2)
void proj_kernel(const float* __restrict__ W,
                 const float* __restrict__ bias,
                 float* __restrict__ out)
{
    __shared__ float As[8][64];
    __shared__ float Bs[8][128];

    const int tid = threadIdx.x;
    const int tx = tid & 15;
    const int ty = tid >> 4;
    const int m0 = blockIdx.y * 64;
    const int n0 = blockIdx.x * 128;

    float acc[4][8] = {};

    const int a_row = tid >> 2;          // 0..63
    const int a_k2  = (tid & 3) * 2;     // 0,2,4,6
    const int b_k   = tid >> 5;
    const int b_col = (tid & 31) * 4;

    for (int k0 = 0; k0 < Cz; k0 += 8) {
        float2 av = *(const float2*)&g_y[(size_t)(m0 + a_row) * Cz + k0 + a_k2];
        As[a_k2 + 0][a_row] = av.x;
        As[a_k2 + 1][a_row] = av.y;
        *(float4*)&Bs[b_k][b_col] =
            *(const float4*)&W[(size_t)(k0 + b_k) * Cz + n0 + b_col];
        __syncthreads();

        #pragma unroll
        for (int kk = 0; kk < 8; kk++) {
            float a[4], b[8];
            *(float4*)&a[0] = *(float4*)&As[kk][ty * 4];
            *(float4*)&b[0] = *(float4*)&Bs[kk][tx * 8];
            *(float4*)&b[4] = *(float4*)&Bs[kk][tx * 8 + 4];
            #pragma unroll
            for (int r = 0; r < 4; r++)
                #pragma unroll
                for (int c = 0; c < 8; c++)
                    acc[r][c] += a[r] * b[c];
        }
        __syncthreads();
    }

    #pragma unroll
    for (int r = 0; r < 4; r++) {
        const int m = m0 + ty * 4 + r;
        float* p = &out[(size_t)m * Cz + n0 + tx * 8];
        float4 o0 = make_float4(acc[r][0] + bias[n0 + tx * 8 + 0],
                                acc[r][1] + bias[n0 + tx * 8 + 1],
                                acc[r][2] + bias[n0 + tx * 8 + 2],
                                acc[r][3] + bias[n0 + tx * 8 + 3]);
        float4 o1 = make_float4(acc[r][4] + bias[n0 + tx * 8 + 4],
                                acc[r][5] + bias[n0 + tx * 8 + 5],
                                acc[r][6] + bias[n0 + tx * 8 + 6],
                                acc[r][7] + bias[n0 + tx * 8 + 7]);
        *(float4*)p       = o0;
        *(float4*)(p + 4) = o1;
    }
}

// ---------------------------------------------------------------------------
extern "C" void kernel_launch(void* const* d_in, const int* in_sizes, int n_in,
                              void* d_out, int out_size)
{
    const float* x        = (const float*)d_in[0];
    const float* c_attn_w = (const float*)d_in[1];
    const float* c_attn_b = (const float*)d_in[2];
    const float* c_proj_w = (const float*)d_in[3];
    const float* c_proj_b = (const float*)d_in[4];
    float* out = (float*)d_out;

    // Opt-in dynamic smem for the attention kernel (70,400 B/block).
    cudaFuncSetAttribute(attn_kernel,
                         cudaFuncAttributeMaxDynamicSharedMemorySize,
                         (int)sizeof(AttnSmem));

    qkv_kernel<<<dim3(N3 / 128, BT / 128), 256>>>(x, c_attn_w, c_attn_b);
    attn_kernel<<<dim3(Tz / 64, Bz * Hz), 256, sizeof(AttnSmem)>>>();
    proj_kernel<<<dim3(Cz / 128, BT / 64), 256>>>(c_proj_w, c_proj_b, out);
}

// round 8
// speedup vs baseline: 1.0016x; 1.0016x over previous
#include <cuda_runtime.h>
#include <math.h>

// Problem constants
#define Bz 2
#define Tz 2048
#define Cz 768
#define Hz 12
#define Dz 64
#define BT (Bz * Tz)     // 4096
#define N3 (3 * Cz)      // 2304

#define F32_NEG_INF (__int_as_float(0xff800000))

// Scratch (allocation-free rule: device globals)
__device__ float g_q[Bz * Hz * Tz * Dz];
__device__ float g_k[Bz * Hz * Tz * Dz];
__device__ float g_v[Bz * Hz * Tz * Dz];
__device__ float g_y[BT * Cz];

// ---------------------------------------------------------------------------
// Kernel 1: QKV GEMM.  qkv = x @ c_attn_w + b, scattered into g_q/g_k/g_v
// laid out [B, H, T, D].  M=4096, N=2304, K=768. 128x128 tile, 8x8 micro.
// ---------------------------------------------------------------------------
__global__ __launch_bounds__(256, 2)
void qkv_kernel(const float* __restrict__ X,
                const float* __restrict__ W,
                const float* __restrict__ bias)
{
    __shared__ float As[8][128];
    __shared__ float Bs[8][128];

    const int tid = threadIdx.x;
    const int tx = tid & 15;
    const int ty = tid >> 4;
    const int m0 = blockIdx.y * 128;
    const int n0 = blockIdx.x * 128;

    float acc[8][8] = {};

    const int a_row = tid >> 1;          // 0..127
    const int a_k4  = (tid & 1) * 4;     // 0 or 4
    const int b_k   = tid >> 5;          // 0..7
    const int b_col = (tid & 31) * 4;    // 0..124

    for (int k0 = 0; k0 < Cz; k0 += 8) {
        float4 av = *(const float4*)&X[(size_t)(m0 + a_row) * Cz + k0 + a_k4];
        As[a_k4 + 0][a_row] = av.x;
        As[a_k4 + 1][a_row] = av.y;
        As[a_k4 + 2][a_row] = av.z;
        As[a_k4 + 3][a_row] = av.w;
        *(float4*)&Bs[b_k][b_col] =
            *(const float4*)&W[(size_t)(k0 + b_k) * N3 + n0 + b_col];
        __syncthreads();

        #pragma unroll
        for (int kk = 0; kk < 8; kk++) {
            float a[8], b[8];
            *(float4*)&a[0] = *(float4*)&As[kk][ty * 8];
            *(float4*)&a[4] = *(float4*)&As[kk][ty * 8 + 4];
            *(float4*)&b[0] = *(float4*)&Bs[kk][tx * 8];
            *(float4*)&b[4] = *(float4*)&Bs[kk][tx * 8 + 4];
            #pragma unroll
            for (int r = 0; r < 8; r++)
                #pragma unroll
                for (int c = 0; c < 8; c++)
                    acc[r][c] += a[r] * b[c];
        }
        __syncthreads();
    }

    // Epilogue: bias + scatter into q/k/v [B,H,T,D].
    // This thread's 8 columns stay within one 64-wide head chunk.
    const int cb   = n0 + tx * 8;        // column in [0, 2304)
    const int part = cb / Cz;            // 0=q,1=k,2=v
    const int cc   = cb % Cz;
    const int h    = cc / Dz;
    const int d0   = cc % Dz;
    float* dst = (part == 0) ? g_q : ((part == 1) ? g_k : g_v);

    float bb[8];
    #pragma unroll
    for (int c = 0; c < 8; c++) bb[c] = bias[cb + c];

    #pragma unroll
    for (int r = 0; r < 8; r++) {
        const int m  = m0 + ty * 8 + r;
        const int bi = m >> 11;          // / 2048
        const int t  = m & 2047;
        float* p = dst + ((size_t)(bi * Hz + h) * Tz + t) * Dz + d0;
        float4 o0 = make_float4(acc[r][0] + bb[0], acc[r][1] + bb[1],
                                acc[r][2] + bb[2], acc[r][3] + bb[3]);
        float4 o1 = make_float4(acc[r][4] + bb[4], acc[r][5] + bb[5],
                                acc[r][6] + bb[6], acc[r][7] + bb[7]);
        *(float4*)p       = o0;
        *(float4*)(p + 4) = o1;
    }
}

// ---------------------------------------------------------------------------
// Kernel 2: Flash attention, fp32. One block = 64 q rows of one (b,h).
// Online softmax. Writes y pre-proj into g_y [B, T, C].
// ---------------------------------------------------------------------------
#define APAD 68
struct AttnSmem {
    float Qt[64][APAD];   // [d][i], pre-scaled by 1/sqrt(D)
    float Kt[64][APAD];   // [d][j]
    float Vs[64][APAD];   // [j][d]
    float Ss[64][APAD];   // scores -> probs
    float m_s[64];
    float l_s[64];
    float alpha_s[64];
};

__global__ __launch_bounds__(256, 2)
void attn_kernel()
{
    extern __shared__ char smbuf[];
    AttnSmem& s = *reinterpret_cast<AttnSmem*>(smbuf);

    const int tid = threadIdx.x;
    const int tx = tid & 15;
    const int ty = tid >> 4;
    const int qt = blockIdx.x;           // q tile (64 rows)
    const int bh = blockIdx.y;           // 0..23
    const int b  = bh / Hz;
    const int h  = bh % Hz;

    const float* Q = g_q + (size_t)bh * Tz * Dz;
    const float* K = g_k + (size_t)bh * Tz * Dz;
    const float* V = g_v + (size_t)bh * Tz * Dz;

    // Load Q tile transposed, pre-scaled by 1/sqrt(64)
    for (int idx = tid; idx < 64 * 16; idx += 256) {
        const int i  = idx >> 4;
        const int d4 = (idx & 15) * 4;
        float4 val = *(const float4*)&Q[(size_t)(qt * 64 + i) * Dz + d4];
        s.Qt[d4 + 0][i] = val.x * 0.125f;
        s.Qt[d4 + 1][i] = val.y * 0.125f;
        s.Qt[d4 + 2][i] = val.z * 0.125f;
        s.Qt[d4 + 3][i] = val.w * 0.125f;
    }
    if (tid < 64) { s.m_s[tid] = F32_NEG_INF; s.l_s[tid] = 0.0f; }

    float acc[4][4] = {};
    const int row = tid >> 2;            // 0..63
    const int seg = tid & 3;             // quarter of the row
    const float L2E = 1.4426950408889634f;
    __syncthreads();

    for (int kt = 0; kt <= qt; kt++) {
        // Load K transposed and V natural
        for (int idx = tid; idx < 1024; idx += 256) {
            const int j  = idx >> 4;
            const int d4 = (idx & 15) * 4;
            float4 val = *(const float4*)&K[(size_t)(kt * 64 + j) * Dz + d4];
            s.Kt[d4 + 0][j] = val.x;
            s.Kt[d4 + 1][j] = val.y;
            s.Kt[d4 + 2][j] = val.z;
            s.Kt[d4 + 3][j] = val.w;
        }
        for (int idx = tid; idx < 1024; idx += 256) {
            const int j  = idx >> 4;
            const int d4 = (idx & 15) * 4;
            *(float4*)&s.Vs[j][d4] =
                *(const float4*)&V[(size_t)(kt * 64 + j) * Dz + d4];
        }
        __syncthreads();

        // S = (Q*scale) @ K^T   (4x4 microtile per thread)
        float sv[4][4] = {};
        #pragma unroll 8
        for (int d = 0; d < 64; d++) {
            float4 af = *(float4*)&s.Qt[d][ty * 4];
            float4 bf = *(float4*)&s.Kt[d][tx * 4];
            float aa[4] = {af.x, af.y, af.z, af.w};
            float bb[4] = {bf.x, bf.y, bf.z, bf.w};
            #pragma unroll
            for (int r = 0; r < 4; r++)
                #pragma unroll
                for (int c = 0; c < 4; c++)
                    sv[r][c] += aa[r] * bb[c];
        }
        if (kt == qt) {
            #pragma unroll
            for (int r = 0; r < 4; r++)
                #pragma unroll
                for (int c = 0; c < 4; c++)
                    if (tx * 4 + c > ty * 4 + r) sv[r][c] = F32_NEG_INF;
        }
        #pragma unroll
        for (int r = 0; r < 4; r++)
            *(float4*)&s.Ss[ty * 4 + r][tx * 4] =
                make_float4(sv[r][0], sv[r][1], sv[r][2], sv[r][3]);
        __syncthreads();

        // Online softmax: 4 threads per row (quad reduce via shfl)
        float mx = F32_NEG_INF;
        #pragma unroll
        for (int e = 0; e < 16; e++)
            mx = fmaxf(mx, s.Ss[row][seg * 16 + e]);
        mx = fmaxf(mx, __shfl_xor_sync(0xffffffffu, mx, 1));
        mx = fmaxf(mx, __shfl_xor_sync(0xffffffffu, mx, 2));
        const float mold = s.m_s[row];
        const float mnew = fmaxf(mold, mx);
        float sum = 0.0f;
        #pragma unroll
        for (int e = 0; e < 16; e++) {
            float p = exp2f((s.Ss[row][seg * 16 + e] - mnew) * L2E);
            s.Ss[row][seg * 16 + e] = p;
            sum += p;
        }
        sum += __shfl_xor_sync(0xffffffffu, sum, 1);
        sum += __shfl_xor_sync(0xffffffffu, sum, 2);
        if (seg == 0) {
            const float alpha = exp2f((mold - mnew) * L2E);
            s.alpha_s[row] = alpha;
            s.l_s[row] = s.l_s[row] * alpha + sum;
            s.m_s[row] = mnew;
        }
        __syncthreads();

        // Rescale O and accumulate P @ V
        float ar[4];
        #pragma unroll
        for (int r = 0; r < 4; r++) ar[r] = s.alpha_s[ty * 4 + r];
        #pragma unroll
        for (int r = 0; r < 4; r++)
            #pragma unroll
            for (int c = 0; c < 4; c++)
                acc[r][c] *= ar[r];

        #pragma unroll 8
        for (int kk = 0; kk < 64; kk++) {
            float4 vf = *(float4*)&s.Vs[kk][tx * 4];
            float vb[4] = {vf.x, vf.y, vf.z, vf.w};
            float p[4];
            #pragma unroll
            for (int r = 0; r < 4; r++) p[r] = s.Ss[ty * 4 + r][kk];
            #pragma unroll
            for (int r = 0; r < 4; r++)
                #pragma unroll
                for (int c = 0; c < 4; c++)
                    acc[r][c] += p[r] * vb[c];
        }
        __syncthreads();
    }

    // Normalize and write y[b, t, h*D + d]
    float inv[4];
    #pragma unroll
    for (int r = 0; r < 4; r++) inv[r] = 1.0f / s.l_s[ty * 4 + r];
    #pragma unroll
    for (int r = 0; r < 4; r++) {
        const int tglob = qt * 64 + ty * 4 + r;
        float4 o = make_float4(acc[r][0] * inv[r], acc[r][1] * inv[r],
                               acc[r][2] * inv[r], acc[r][3] * inv[r]);
        *(float4*)&g_y[((size_t)b * Tz + tglob) * Cz + h * Dz + tx * 4] = o;
    }
}

// ---------------------------------------------------------------------------
// Kernel 3: output projection. out = g_y @ c_proj_w + b.
// M=4096, N=768, K=768. 64x128 tile, 4x8 micro. grid (6, 64).
// ---------------------------------------------------------------------------
__global__ __launch_bounds__(256, 2)
void proj_kernel(const float* __restrict__ W,
                 const float* __restrict__ bias,
                 float* __restrict__ out)
{
    __shared__ float As[8][64];
    __shared__ float Bs[8][128];

    const int tid = threadIdx.x;
    const int tx = tid & 15;
    const int ty = tid >> 4;
    const int m0 = blockIdx.y * 64;
    const int n0 = blockIdx.x * 128;

    float acc[4][8] = {};

    const int a_row = tid >> 2;          // 0..63
    const int a_k2  = (tid & 3) * 2;     // 0,2,4,6
    const int b_k   = tid >> 5;
    const int b_col = (tid & 31) * 4;

    for (int k0 = 0; k0 < Cz; k0 += 8) {
        float2 av = *(const float2*)&g_y[(size_t)(m0 + a_row) * Cz + k0 + a_k2];
        As[a_k2 + 0][a_row] = av.x;
        As[a_k2 + 1][a_row] = av.y;
        *(float4*)&Bs[b_k][b_col] =
            *(const float4*)&W[(size_t)(k0 + b_k) * Cz + n0 + b_col];
        __syncthreads();

        #pragma unroll
        for (int kk = 0; kk < 8; kk++) {
            float a[4], b[8];
            *(float4*)&a[0] = *(float4*)&As[kk][ty * 4];
            *(float4*)&b[0] = *(float4*)&Bs[kk][tx * 8];
            *(float4*)&b[4] = *(float4*)&Bs[kk][tx * 8 + 4];
            #pragma unroll
            for (int r = 0; r < 4; r++)
                #pragma unroll
                for (int c = 0; c < 8; c++)
                    acc[r][c] += a[r] * b[c];
        }
        __syncthreads();
    }

    #pragma unroll
    for (int r = 0; r < 4; r++) {
        const int m = m0 + ty * 4 + r;
        float* p = &out[(size_t)m * Cz + n0 + tx * 8];
        float4 o0 = make_float4(acc[r][0] + bias[n0 + tx * 8 + 0],
                                acc[r][1] + bias[n0 + tx * 8 + 1],
                                acc[r][2] + bias[n0 + tx * 8 + 2],
                                acc[r][3] + bias[n0 + tx * 8 + 3]);
        float4 o1 = make_float4(acc[r][4] + bias[n0 + tx * 8 + 4],
                                acc[r][5] + bias[n0 + tx * 8 + 5],
                                acc[r][6] + bias[n0 + tx * 8 + 6],
                                acc[r][7] + bias[n0 + tx * 8 + 7]);
        *(float4*)p       = o0;
        *(float4*)(p + 4) = o1;
    }
}

// ---------------------------------------------------------------------------
extern "C" void kernel_launch(void* const* d_in, const int* in_sizes, int n_in,
                              void* d_out, int out_size)
{
    const float* x        = (const float*)d_in[0];
    const float* c_attn_w = (const float*)d_in[1];
    const float* c_attn_b = (const float*)d_in[2];
    const float* c_proj_w = (const float*)d_in[3];
    const float* c_proj_b = (const float*)d_in[4];
    float* out = (float*)d_out;

    // Opt-in dynamic smem for the attention kernel (70,400 B/block).
    cudaFuncSetAttribute(attn_kernel,
                         cudaFuncAttributeMaxDynamicSharedMemorySize,
                         (int)sizeof(AttnSmem));

    qkv_kernel<<<dim3(N3 / 128, BT / 128), 256>>>(x, c_attn_w, c_attn_b);
    attn_kernel<<<dim3(Tz / 64, Bz * Hz), 256, sizeof(AttnSmem)>>>();
    proj_kernel<<<dim3(Cz / 128, BT / 64), 256>>>(c_proj_w, c_proj_b, out);
}

// round 11
// speedup vs baseline: 1.0022x; 1.0006x over previous
#include <cuda_runtime.h>
#include <math.h>

// Problem constants
#define Bz 2
#define Tz 2048
#define Cz 768
#define Hz 12
#define Dz 64
#define BT (Bz * Tz)     // 4096
#define N3 (3 * Cz)      // 2304

#define F32_NEG_INF (__int_as_float(0xff800000))

// Scratch (allocation-free rule: device globals)
__device__ float g_q[Bz * Hz * Tz * Dz];
__device__ float g_k[Bz * Hz * Tz * Dz];
__device__ float g_v[Bz * Hz * Tz * Dz];
__device__ float g_y[BT * Cz];

// ---------------------------------------------------------------------------
// Kernel 1: QKV GEMM.  qkv = x @ c_attn_w + b, scattered into g_q/g_k/g_v
// laid out [B, H, T, D].  M=4096, N=2304, K=768. 128x128 tile, 8x8 micro.
// ---------------------------------------------------------------------------
__global__ __launch_bounds__(256, 2)
void qkv_kernel(const float* __restrict__ X,
                const float* __restrict__ W,
                const float* __restrict__ bias)
{
    __shared__ float As[8][128];
    __shared__ float Bs[8][128];

    const int tid = threadIdx.x;
    const int tx = tid & 15;
    const int ty = tid >> 4;
    const int m0 = blockIdx.y * 128;
    const int n0 = blockIdx.x * 128;

    float acc[8][8] = {};

    const int a_row = tid >> 1;          // 0..127
    const int a_k4  = (tid & 1) * 4;     // 0 or 4
    const int b_k   = tid >> 5;          // 0..7
    const int b_col = (tid & 31) * 4;    // 0..124

    for (int k0 = 0; k0 < Cz; k0 += 8) {
        float4 av = *(const float4*)&X[(size_t)(m0 + a_row) * Cz + k0 + a_k4];
        As[a_k4 + 0][a_row] = av.x;
        As[a_k4 + 1][a_row] = av.y;
        As[a_k4 + 2][a_row] = av.z;
        As[a_k4 + 3][a_row] = av.w;
        *(float4*)&Bs[b_k][b_col] =
            *(const float4*)&W[(size_t)(k0 + b_k) * N3 + n0 + b_col];
        __syncthreads();

        #pragma unroll
        for (int kk = 0; kk < 8; kk++) {
            float a[8], b[8];
            *(float4*)&a[0] = *(float4*)&As[kk][ty * 8];
            *(float4*)&a[4] = *(float4*)&As[kk][ty * 8 + 4];
            *(float4*)&b[0] = *(float4*)&Bs[kk][tx * 8];
            *(float4*)&b[4] = *(float4*)&Bs[kk][tx * 8 + 4];
            #pragma unroll
            for (int r = 0; r < 8; r++)
                #pragma unroll
                for (int c = 0; c < 8; c++)
                    acc[r][c] += a[r] * b[c];
        }
        __syncthreads();
    }

    // Epilogue: bias + scatter into q/k/v [B,H,T,D].
    // This thread's 8 columns stay within one 64-wide head chunk.
    const int cb   = n0 + tx * 8;        // column in [0, 2304)
    const int part = cb / Cz;            // 0=q,1=k,2=v
    const int cc   = cb % Cz;
    const int h    = cc / Dz;
    const int d0   = cc % Dz;
    float* dst = (part == 0) ? g_q : ((part == 1) ? g_k : g_v);

    float bb[8];
    #pragma unroll
    for (int c = 0; c < 8; c++) bb[c] = bias[cb + c];

    #pragma unroll
    for (int r = 0; r < 8; r++) {
        const int m  = m0 + ty * 8 + r;
        const int bi = m >> 11;          // / 2048
        const int t  = m & 2047;
        float* p = dst + ((size_t)(bi * Hz + h) * Tz + t) * Dz + d0;
        float4 o0 = make_float4(acc[r][0] + bb[0], acc[r][1] + bb[1],
                                acc[r][2] + bb[2], acc[r][3] + bb[3]);
        float4 o1 = make_float4(acc[r][4] + bb[4], acc[r][5] + bb[5],
                                acc[r][6] + bb[6], acc[r][7] + bb[7]);
        *(float4*)p       = o0;
        *(float4*)(p + 4) = o1;
    }
}

// ---------------------------------------------------------------------------
// Kernel 2: Flash attention, fp32. One block = 64 q rows of one (b,h).
// Online softmax. Writes y pre-proj into g_y [B, T, C].
// ---------------------------------------------------------------------------
#define APAD 68
struct AttnSmem {
    float Qt[64][APAD];   // [d][i], pre-scaled by 1/sqrt(D)
    float Kt[64][APAD];   // [d][j]
    float Vs[64][APAD];   // [j][d]
    float Ss[64][APAD];   // scores -> probs
    float m_s[64];
    float l_s[64];
    float alpha_s[64];
};

__global__ __launch_bounds__(256, 2)
void attn_kernel()
{
    extern __shared__ char smbuf[];
    AttnSmem& s = *reinterpret_cast<AttnSmem*>(smbuf);

    const int tid = threadIdx.x;
    const int tx = tid & 15;
    const int ty = tid >> 4;
    const int qt = blockIdx.x;           // q tile (64 rows)
    const int bh = blockIdx.y;           // 0..23
    const int b  = bh / Hz;
    const int h  = bh % Hz;

    const float* Q = g_q + (size_t)bh * Tz * Dz;
    const float* K = g_k + (size_t)bh * Tz * Dz;
    const float* V = g_v + (size_t)bh * Tz * Dz;

    // Load Q tile transposed, pre-scaled by 1/sqrt(64)
    for (int idx = tid; idx < 64 * 16; idx += 256) {
        const int i  = idx >> 4;
        const int d4 = (idx & 15) * 4;
        float4 val = *(const float4*)&Q[(size_t)(qt * 64 + i) * Dz + d4];
        s.Qt[d4 + 0][i] = val.x * 0.125f;
        s.Qt[d4 + 1][i] = val.y * 0.125f;
        s.Qt[d4 + 2][i] = val.z * 0.125f;
        s.Qt[d4 + 3][i] = val.w * 0.125f;
    }
    if (tid < 64) { s.m_s[tid] = F32_NEG_INF; s.l_s[tid] = 0.0f; }

    float acc[4][4] = {};
    const int row = tid >> 2;            // 0..63
    const int seg = tid & 3;             // quarter of the row
    const float L2E = 1.4426950408889634f;
    __syncthreads();

    for (int kt = 0; kt <= qt; kt++) {
        // Load K transposed and V natural
        for (int idx = tid; idx < 1024; idx += 256) {
            const int j  = idx >> 4;
            const int d4 = (idx & 15) * 4;
            float4 val = *(const float4*)&K[(size_t)(kt * 64 + j) * Dz + d4];
            s.Kt[d4 + 0][j] = val.x;
            s.Kt[d4 + 1][j] = val.y;
            s.Kt[d4 + 2][j] = val.z;
            s.Kt[d4 + 3][j] = val.w;
        }
        for (int idx = tid; idx < 1024; idx += 256) {
            const int j  = idx >> 4;
            const int d4 = (idx & 15) * 4;
            *(float4*)&s.Vs[j][d4] =
                *(const float4*)&V[(size_t)(kt * 64 + j) * Dz + d4];
        }
        __syncthreads();

        // S = (Q*scale) @ K^T   (4x4 microtile per thread)
        float sv[4][4] = {};
        #pragma unroll 8
        for (int d = 0; d < 64; d++) {
            float4 af = *(float4*)&s.Qt[d][ty * 4];
            float4 bf = *(float4*)&s.Kt[d][tx * 4];
            float aa[4] = {af.x, af.y, af.z, af.w};
            float bb[4] = {bf.x, bf.y, bf.z, bf.w};
            #pragma unroll
            for (int r = 0; r < 4; r++)
                #pragma unroll
                for (int c = 0; c < 4; c++)
                    sv[r][c] += aa[r] * bb[c];
        }
        if (kt == qt) {
            #pragma unroll
            for (int r = 0; r < 4; r++)
                #pragma unroll
                for (int c = 0; c < 4; c++)
                    if (tx * 4 + c > ty * 4 + r) sv[r][c] = F32_NEG_INF;
        }
        #pragma unroll
        for (int r = 0; r < 4; r++)
            *(float4*)&s.Ss[ty * 4 + r][tx * 4] =
                make_float4(sv[r][0], sv[r][1], sv[r][2], sv[r][3]);
        __syncthreads();

        // Online softmax: 4 threads per row (quad reduce via shfl)
        float mx = F32_NEG_INF;
        #pragma unroll
        for (int e = 0; e < 16; e++)
            mx = fmaxf(mx, s.Ss[row][seg * 16 + e]);
        mx = fmaxf(mx, __shfl_xor_sync(0xffffffffu, mx, 1));
        mx = fmaxf(mx, __shfl_xor_sync(0xffffffffu, mx, 2));
        const float mold = s.m_s[row];
        const float mnew = fmaxf(mold, mx);
        float sum = 0.0f;
        #pragma unroll
        for (int e = 0; e < 16; e++) {
            float p = exp2f((s.Ss[row][seg * 16 + e] - mnew) * L2E);
            s.Ss[row][seg * 16 + e] = p;
            sum += p;
        }
        sum += __shfl_xor_sync(0xffffffffu, sum, 1);
        sum += __shfl_xor_sync(0xffffffffu, sum, 2);
        if (seg == 0) {
            const float alpha = exp2f((mold - mnew) * L2E);
            s.alpha_s[row] = alpha;
            s.l_s[row] = s.l_s[row] * alpha + sum;
            s.m_s[row] = mnew;
        }
        __syncthreads();

        // Rescale O and accumulate P @ V
        float ar[4];
        #pragma unroll
        for (int r = 0; r < 4; r++) ar[r] = s.alpha_s[ty * 4 + r];
        #pragma unroll
        for (int r = 0; r < 4; r++)
            #pragma unroll
            for (int c = 0; c < 4; c++)
                acc[r][c] *= ar[r];

        #pragma unroll 8
        for (int kk = 0; kk < 64; kk++) {
            float4 vf = *(float4*)&s.Vs[kk][tx * 4];
            float vb[4] = {vf.x, vf.y, vf.z, vf.w};
            float p[4];
            #pragma unroll
            for (int r = 0; r < 4; r++) p[r] = s.Ss[ty * 4 + r][kk];
            #pragma unroll
            for (int r = 0; r < 4; r++)
                #pragma unroll
                for (int c = 0; c < 4; c++)
                    acc[r][c] += p[r] * vb[c];
        }
        __syncthreads();
    }

    // Normalize and write y[b, t, h*D + d]
    float inv[4];
    #pragma unroll
    for (int r = 0; r < 4; r++) inv[r] = 1.0f / s.l_s[ty * 4 + r];
    #pragma unroll
    for (int r = 0; r < 4; r++) {
        const int tglob = qt * 64 + ty * 4 + r;
        float4 o = make_float4(acc[r][0] * inv[r], acc[r][1] * inv[r],
                               acc[r][2] * inv[r], acc[r][3] * inv[r]);
        *(float4*)&g_y[((size_t)b * Tz + tglob) * Cz + h * Dz + tx * 4] = o;
    }
}

// ---------------------------------------------------------------------------
// Kernel 3: output projection. out = g_y @ c_proj_w + b.
// M=4096, N=768, K=768. 64x128 tile, 4x8 micro. grid (6, 64).
// ---------------------------------------------------------------------------
__global__ __launch_bounds__(256, 2)
void proj_kernel(const float* __restrict__ W,
                 const float* __restrict__ bias,
                 float* __restrict__ out)
{
    __shared__ float As[8][64];
    __shared__ float Bs[8][128];

    const int tid = threadIdx.x;
    const int tx = tid & 15;
    const int ty = tid >> 4;
    const int m0 = blockIdx.y * 64;
    const int n0 = blockIdx.x * 128;

    float acc[4][8] = {};

    const int a_row = tid >> 2;          // 0..63
    const int a_k2  = (tid & 3) * 2;     // 0,2,4,6
    const int b_k   = tid >> 5;
    const int b_col = (tid & 31) * 4;

    for (int k0 = 0; k0 < Cz; k0 += 8) {
        float2 av = *(const float2*)&g_y[(size_t)(m0 + a_row) * Cz + k0 + a_k2];
        As[a_k2 + 0][a_row] = av.x;
        As[a_k2 + 1][a_row] = av.y;
        *(float4*)&Bs[b_k][b_col] =
            *(const float4*)&W[(size_t)(k0 + b_k) * Cz + n0 + b_col];
        __syncthreads();

        #pragma unroll
        for (int kk = 0; kk < 8; kk++) {
            float a[4], b[8];
            *(float4*)&a[0] = *(float4*)&As[kk][ty * 4];
            *(float4*)&b[0] = *(float4*)&Bs[kk][tx * 8];
            *(float4*)&b[4] = *(float4*)&Bs[kk][tx * 8 + 4];
            #pragma unroll
            for (int r = 0; r < 4; r++)
                #pragma unroll
                for (int c = 0; c < 8; c++)
                    acc[r][c] += a[r] * b[c];
        }
        __syncthreads();
    }

    #pragma unroll
    for (int r = 0; r < 4; r++) {
        const int m = m0 + ty * 4 + r;
        float* p = &out[(size_t)m * Cz + n0 + tx * 8];
        float4 o0 = make_float4(acc[r][0] + bias[n0 + tx * 8 + 0],
                                acc[r][1] + bias[n0 + tx * 8 + 1],
                                acc[r][2] + bias[n0 + tx * 8 + 2],
                                acc[r][3] + bias[n0 + tx * 8 + 3]);
        float4 o1 = make_float4(acc[r][4] + bias[n0 + tx * 8 + 4],
                                acc[r][5] + bias[n0 + tx * 8 + 5],
                                acc[r][6] + bias[n0 + tx * 8 + 6],
                                acc[r][7] + bias[n0 + tx * 8 + 7]);
        *(float4*)p       = o0;
        *(float4*)(p + 4) = o1;
    }
}

// ---------------------------------------------------------------------------
extern "C" void kernel_launch(void* const* d_in, const int* in_sizes, int n_in,
                              void* d_out, int out_size)
{
    const float* x        = (const float*)d_in[0];
    const float* c_attn_w = (const float*)d_in[1];
    const float* c_attn_b = (const float*)d_in[2];
    const float* c_proj_w = (const float*)d_in[3];
    const float* c_proj_b = (const float*)d_in[4];
    float* out = (float*)d_out;

    // Opt-in dynamic smem for the attention kernel (70,400 B/block).
    cudaFuncSetAttribute(attn_kernel,
                         cudaFuncAttributeMaxDynamicSharedMemorySize,
                         (int)sizeof(AttnSmem));

    qkv_kernel<<<dim3(N3 / 128, BT / 128), 256>>>(x, c_attn_w, c_attn_b);
    attn_kernel<<<dim3(Tz / 64, Bz * Hz), 256, sizeof(AttnSmem)>>>();
    proj_kernel<<<dim3(Cz / 128, BT / 64), 256>>>(c_proj_w, c_proj_b, out);
}